// round 15
// baseline (speedup 1.0000x reference)
#include <cuda_runtime.h>
#include <cuda_fp16.h>
#include <cstdint>

// FlashAttention B=2,H=16,N=4096,D=64 fp32. logits=(q.k)/64.
// HMMA mma.sync fp16 path (plain-sm_103 toolchain; tcgen05/fp8 ruled out).
// R14 = R13 pipeline (BN=128, NBUF=3 ring, dist-1 prefetch, Q in slot 2,
// per-SM stagger) with BM=64 / warp-M=16: grid 2048 units instead of 1024,
// cutting the wave-quantization tail (1024/296 -> makespan 4 vs ideal 3.46)
// to near zero (2048/296 -> 7 vs 6.92). Per-unit instruction mix unchanged.

namespace {
constexpr int BHn = 32;
constexpr int NSEQ = 4096;
constexpr int DH = 64;
constexpr int BM = 64;
constexpr int BN = 128;
constexpr int NKV = NSEQ / BN;  // 32
constexpr int NTH = 128;        // 4 warps, warp-M = 16
constexpr int LDS = 72;         // smem row stride (halves)
constexpr int NBUF = 3;
constexpr float QS2 = 1.4426950408889634f / 64.0f;  // log2(e)/64
constexpr size_t ELEMS = (size_t)BHn * NSEQ * DH;

__device__ __half g_kh[ELEMS];
__device__ __half g_vh[ELEMS];
__device__ unsigned int g_smctr[256];  // per-SM arrival counters

// smem (halves): ring slot i at i*KVH (K then V). Q staging aliases slot 2.
constexpr int KVH = 2 * BN * LDS;  // 18432 halves per buffer
constexpr int OQ = 2 * KVH;        // Q staging = slot 2 (first written at t=2)
constexpr int SMEM_BYTES = NBUF * KVH * 2;  // 110592 B

__device__ __forceinline__ uint32_t s2u(const void* p) {
  return (uint32_t)__cvta_generic_to_shared(p);
}
__device__ __forceinline__ void cpa16(uint32_t dst, const void* src) {
  asm volatile("cp.async.cg.shared.global [%0], [%1], 16;" :: "r"(dst), "l"(src));
}
__device__ __forceinline__ void mbar_init(uint32_t a, uint32_t c) {
  asm volatile("mbarrier.init.shared.b64 [%0], %1;" :: "r"(a), "r"(c) : "memory");
}
__device__ __forceinline__ void mbar_arrive(uint32_t a) {
  asm volatile("mbarrier.arrive.shared.b64 _, [%0];" :: "r"(a) : "memory");
}
__device__ __forceinline__ void cpa_arrive(uint32_t a) {
  asm volatile("cp.async.mbarrier.arrive.noinc.shared.b64 [%0];" :: "r"(a) : "memory");
}
__device__ __forceinline__ void mbar_wait(uint32_t a, uint32_t ph) {
  asm volatile(
      "{\n\t.reg .pred P;\n"
      "W%=:\n\t"
      "mbarrier.try_wait.parity.acquire.cta.shared::cta.b64 P, [%0], %1, 0x989680;\n\t"
      "@P bra D%=;\n\t"
      "bra W%=;\n"
      "D%=:\n\t}"
      :: "r"(a), "r"(ph) : "memory");
}
__device__ __forceinline__ void ldsm4(uint32_t* r, uint32_t a) {
  asm volatile("ldmatrix.sync.aligned.m8n8.x4.shared.b16 {%0,%1,%2,%3}, [%4];"
               : "=r"(r[0]), "=r"(r[1]), "=r"(r[2]), "=r"(r[3]) : "r"(a));
}
__device__ __forceinline__ void ldsm4t(uint32_t* r, uint32_t a) {
  asm volatile("ldmatrix.sync.aligned.m8n8.x4.trans.shared.b16 {%0,%1,%2,%3}, [%4];"
               : "=r"(r[0]), "=r"(r[1]), "=r"(r[2]), "=r"(r[3]) : "r"(a));
}
__device__ __forceinline__ void mma16816(float* c, const uint32_t* a, const uint32_t* b) {
  asm volatile(
      "mma.sync.aligned.m16n8k16.row.col.f32.f16.f16.f32 "
      "{%0,%1,%2,%3}, {%4,%5,%6,%7}, {%8,%9}, {%0,%1,%2,%3};"
      : "+f"(c[0]), "+f"(c[1]), "+f"(c[2]), "+f"(c[3])
      : "r"(a[0]), "r"(a[1]), "r"(a[2]), "r"(a[3]), "r"(b[0]), "r"(b[1]));
}
__device__ __forceinline__ uint32_t pack2(float x, float y) {
  __half2 h = __floats2half2_rn(x, y);
  return *reinterpret_cast<uint32_t*>(&h);
}
__device__ __forceinline__ uint32_t ex2h2(uint32_t x) {
  uint32_t y;
  asm("ex2.approx.f16x2 %0, %1;" : "=r"(y) : "r"(x));
  return y;
}
__device__ __forceinline__ __half2 u2h2(uint32_t x) {
  return *reinterpret_cast<__half2*>(&x);
}
}  // namespace

// -------- prep: K,V fp32 -> fp16 ---------------------------------------------
__global__ void prep_kernel(const float* __restrict__ k, const float* __restrict__ v) {
  size_t i = (size_t)blockIdx.x * blockDim.x + threadIdx.x;
  const float4 fk = reinterpret_cast<const float4*>(k)[i];
  const float4 fv = reinterpret_cast<const float4*>(v)[i];
  reinterpret_cast<uint2*>(g_kh)[i] = make_uint2(pack2(fk.x, fk.y), pack2(fk.z, fk.w));
  reinterpret_cast<uint2*>(g_vh)[i] = make_uint2(pack2(fv.x, fv.y), pack2(fv.z, fv.w));
}

// -------- main attention kernel ----------------------------------------------
__global__ __launch_bounds__(NTH, 2)
void fa_hmma_kernel(const float* __restrict__ qg, float* __restrict__ out) {
  extern __shared__ __half sm[];
  __shared__ uint64_t barsto[2 * NBUF];  // full[0..2], empty[0..2]
  __shared__ int srank;
  const uint32_t sb = s2u(sm);
  const uint32_t bfull = s2u(&barsto[0]);
  const uint32_t bempty = s2u(&barsto[NBUF]);

  const int tid = threadIdx.x;
  const int lane = tid & 31, warp = tid >> 5;
  const int mi = lane >> 3;
  const int li = lane & 7;
  const int bh = blockIdx.y, mblk = blockIdx.x;

  const float* qsrc = qg + ((size_t)bh * NSEQ + (size_t)mblk * BM) * DH;
  const __half* ksrc = g_kh + (size_t)bh * NSEQ * DH;
  const __half* vsrc = g_vh + (size_t)bh * NSEQ * DH;

  if (tid == 0) {
#pragma unroll
    for (int i = 0; i < NBUF; i++) {
      mbar_init(bfull + 8 * i, NTH);
      mbar_init(bempty + 8 * i, NTH);
    }
    uint32_t smid;
    asm("mov.u32 %0, %%smid;" : "=r"(smid));
    srank = (int)(atomicAdd(&g_smctr[smid & 255], 1u) & 1u);
  }
  __syncthreads();

  // ---- prologue: start KV tile 0 into slot 0 (cp.async) ----
  {
#pragma unroll
    for (int i = 0; i < 8; i++) {  // K: 128 rows x 8 chunks; V same
      int idx = i * NTH + tid;
      int r = idx >> 3, c = (idx & 7) << 3;
      cpa16(sb + (uint32_t)(r * LDS + c) * 2, ksrc + r * DH + c);
      cpa16(sb + (uint32_t)(BN * LDS + r * LDS + c) * 2, vsrc + r * DH + c);
    }
    cpa_arrive(bfull + 0);
  }
  // Q (64 rows): fp32 LDG -> scale(log2 domain) -> fp16 STS into slot-2 staging
#pragma unroll
  for (int i = 0; i < 8; i++) {
    int idx = i * NTH + tid;
    int r = idx >> 4, c = (idx & 15) << 2;
    float4 f = *reinterpret_cast<const float4*>(qsrc + r * DH + c);
    *reinterpret_cast<uint2*>(&sm[OQ + r * LDS + c]) =
        make_uint2(pack2(f.x * QS2, f.y * QS2), pack2(f.z * QS2, f.w * QS2));
  }
  __syncthreads();  // Q visible

  // ---- Q A-fragments (warp-M = 16) ----
  uint32_t qa[4][4];
#pragma unroll
  for (int kt = 0; kt < 4; kt++) {
    int row = warp * 16 + (mi & 1) * 8 + li;
    int col = kt * 16 + (mi >> 1) * 8;
    ldsm4(qa[kt], s2u(&sm[OQ + row * LDS + col]));
  }
  __syncthreads();  // all warps done reading Q: slot 2 may be overwritten (t=2)

  // ---- cross-CTA phase stagger ----
  if (srank) {
    uint32_t t0 = (uint32_t)clock();
    while ((uint32_t)clock() - t0 < 1200u) {}
  }

  float oacc[8][4];
#pragma unroll
  for (int i = 0; i < 8; i++)
#pragma unroll
    for (int j = 0; j < 4; j++) oacc[i][j] = 0.f;
  float lsum[2] = {0.f, 0.f};

#pragma unroll 1
  for (int t = 0; t < NKV; t++) {
    const int buf = t % 3;
    const int kb = buf * KVH;
    const int vb = kb + BN * LDS;

    // ---- prefetch tile t+1 (distance 1 at loop top: slack = 1 full tile) ----
    const int u = t + 1;
    if (u < NKV) {
      const int pb = u % 3;
      if (u >= 3) mbar_wait(bempty + 8 * pb, (uint32_t)(((u - 3) / 3) & 1));
      const __half* kn = ksrc + (size_t)u * BN * DH;
      const __half* vn = vsrc + (size_t)u * BN * DH;
      const int ob = pb * KVH;
#pragma unroll
      for (int i = 0; i < 8; i++) {
        int idx = i * NTH + tid;
        int r = idx >> 3, c = (idx & 7) << 3;
        cpa16(sb + (uint32_t)(ob + r * LDS + c) * 2, kn + r * DH + c);
        cpa16(sb + (uint32_t)(ob + BN * LDS + r * LDS + c) * 2, vn + r * DH + c);
      }
      cpa_arrive(bfull + 8 * pb);
    }

    mbar_wait(bfull + 8 * buf, (uint32_t)((t / 3) & 1));

    // ---- S = Q @ K^T (16 x 128 per warp) ----
    float sacc[16][4];
#pragma unroll
    for (int i = 0; i < 16; i++)
#pragma unroll
      for (int j = 0; j < 4; j++) sacc[i][j] = 0.f;

#pragma unroll
    for (int kt = 0; kt < 4; kt++)
#pragma unroll
      for (int p = 0; p < 8; p++) {
        int row = p * 16 + (mi >> 1) * 8 + li;
        int col = kt * 16 + (mi & 1) * 8;
        uint32_t bf[4];
        ldsm4(bf, s2u(&sm[kb + row * LDS + col]));
        mma16816(sacc[2 * p], qa[kt], bf);
        mma16816(sacc[2 * p + 1], qa[kt], bf + 2);
      }

    // ---- exp (f16x2) + PV, per 16-col group ----
    __half2 a0 = __float2half2_rn(0.f), a1 = a0;
#pragma unroll
    for (int g = 0; g < 8; g++) {
      uint32_t pa[4];
      pa[0] = ex2h2(pack2(sacc[2 * g][0], sacc[2 * g][1]));
      pa[1] = ex2h2(pack2(sacc[2 * g][2], sacc[2 * g][3]));
      pa[2] = ex2h2(pack2(sacc[2 * g + 1][0], sacc[2 * g + 1][1]));
      pa[3] = ex2h2(pack2(sacc[2 * g + 1][2], sacc[2 * g + 1][3]));
      a0 = __hadd2(a0, __hadd2(u2h2(pa[0]), u2h2(pa[2])));
      a1 = __hadd2(a1, __hadd2(u2h2(pa[1]), u2h2(pa[3])));
#pragma unroll
      for (int d = 0; d < 4; d++) {
        int row = g * 16 + (mi & 1) * 8 + li;
        int col = (2 * d + (mi >> 1)) * 8;
        uint32_t bf[4];
        ldsm4t(bf, s2u(&sm[vb + row * LDS + col]));
        mma16816(oacc[2 * d], pa, bf);
        mma16816(oacc[2 * d + 1], pa, bf + 2);
      }
    }
    lsum[0] += __low2float(a0) + __high2float(a0);
    lsum[1] += __low2float(a1) + __high2float(a1);

    mbar_arrive(bempty + 8 * buf);  // done reading buf
  }

  // ---- epilogue: O / max(l, eps) ----
#pragma unroll
  for (int h = 0; h < 2; h++) {
    float ls = lsum[h];
    ls += __shfl_xor_sync(0xffffffffu, ls, 1);
    ls += __shfl_xor_sync(0xffffffffu, ls, 2);
    float inv = 1.0f / fmaxf(ls, 1e-6f);
    int row = mblk * BM + warp * 16 + h * 8 + (lane >> 2);
    float* op = out + ((size_t)bh * NSEQ + row) * DH;
    int cb = (lane & 3) * 2;
#pragma unroll
    for (int nt = 0; nt < 8; nt++) {
      float2 f = make_float2(oacc[nt][2 * h] * inv, oacc[nt][2 * h + 1] * inv);
      *reinterpret_cast<float2*>(op + nt * 8 + cb) = f;
    }
  }
}

extern "C" void kernel_launch(void* const* d_in, const int* in_sizes, int n_in,
                              void* d_out, int out_size) {
  const float* q = (const float*)d_in[0];
  const float* k = (const float*)d_in[1];
  const float* v = (const float*)d_in[2];
  float* out = (float*)d_out;

  prep_kernel<<<(int)(ELEMS / 4 / 256), 256>>>(k, v);

  cudaFuncSetAttribute(fa_hmma_kernel, cudaFuncAttributeMaxDynamicSharedMemorySize,
                       SMEM_BYTES);
  dim3 grid(NSEQ / BM, BHn);  // (64, 32) = 2048 units
  fa_hmma_kernel<<<grid, NTH, SMEM_BYTES>>>(q, out);
}

// round 16
// speedup vs baseline: 1.0427x; 1.0427x over previous
#include <cuda_runtime.h>
#include <cuda_fp16.h>
#include <cstdint>

// FlashAttention B=2,H=4096... (B=2,H=16,N=4096,D=64) fp32. logits=(q.k)/64.
// HMMA mma.sync fp16 path. R15 = R13 kernel body (BM=128/warp-M=32, BN=128,
// NBUF=3 ring, dist-1 prefetch, Q aliased in slot 2, per-SM stagger) with
// SPLIT-KV: grid (32,32,2); each CTA does 16 KV tiles, writes additive
// partials (O,l) to its own scratch buffer; normalize kernel combines.
// 2048 equal units over 296 CTA slots -> wave quantization 7/6.92 = +1.2%
// (vs 4/3.46 = +15.6% at 1024 units).

namespace {
constexpr int BHn = 32;
constexpr int NSEQ = 4096;
constexpr int DH = 64;
constexpr int BM = 128;
constexpr int BN = 128;
constexpr int NKV_L = 16;       // KV tiles per CTA (half of 32)
constexpr int NTH = 128;        // 4 warps, warp-M = 32
constexpr int LDS = 72;         // smem row stride (halves)
constexpr int NBUF = 3;
constexpr float QS2 = 1.4426950408889634f / 64.0f;  // log2(e)/64
constexpr size_t ELEMS = (size_t)BHn * NSEQ * DH;   // 8.4M
constexpr size_t ROWS = (size_t)BHn * NSEQ;         // 131072

__device__ __half g_kh[ELEMS];
__device__ __half g_vh[ELEMS];
__device__ float g_oA[ELEMS];
__device__ float g_oB[ELEMS];
__device__ float g_lA[ROWS];
__device__ float g_lB[ROWS];
__device__ unsigned int g_smctr[256];

// smem (halves): ring slot i at i*KVH (K then V). Q staging aliases slot 2.
constexpr int KVH = 2 * BN * LDS;  // 18432 halves per buffer
constexpr int OQ = 2 * KVH;
constexpr int SMEM_BYTES = NBUF * KVH * 2;  // 110592 B

__device__ __forceinline__ uint32_t s2u(const void* p) {
  return (uint32_t)__cvta_generic_to_shared(p);
}
__device__ __forceinline__ void cpa16(uint32_t dst, const void* src) {
  asm volatile("cp.async.cg.shared.global [%0], [%1], 16;" :: "r"(dst), "l"(src));
}
__device__ __forceinline__ void mbar_init(uint32_t a, uint32_t c) {
  asm volatile("mbarrier.init.shared.b64 [%0], %1;" :: "r"(a), "r"(c) : "memory");
}
__device__ __forceinline__ void mbar_arrive(uint32_t a) {
  asm volatile("mbarrier.arrive.shared.b64 _, [%0];" :: "r"(a) : "memory");
}
__device__ __forceinline__ void cpa_arrive(uint32_t a) {
  asm volatile("cp.async.mbarrier.arrive.noinc.shared.b64 [%0];" :: "r"(a) : "memory");
}
__device__ __forceinline__ void mbar_wait(uint32_t a, uint32_t ph) {
  asm volatile(
      "{\n\t.reg .pred P;\n"
      "W%=:\n\t"
      "mbarrier.try_wait.parity.acquire.cta.shared::cta.b64 P, [%0], %1, 0x989680;\n\t"
      "@P bra D%=;\n\t"
      "bra W%=;\n"
      "D%=:\n\t}"
      :: "r"(a), "r"(ph) : "memory");
}
__device__ __forceinline__ void ldsm4(uint32_t* r, uint32_t a) {
  asm volatile("ldmatrix.sync.aligned.m8n8.x4.shared.b16 {%0,%1,%2,%3}, [%4];"
               : "=r"(r[0]), "=r"(r[1]), "=r"(r[2]), "=r"(r[3]) : "r"(a));
}
__device__ __forceinline__ void ldsm4t(uint32_t* r, uint32_t a) {
  asm volatile("ldmatrix.sync.aligned.m8n8.x4.trans.shared.b16 {%0,%1,%2,%3}, [%4];"
               : "=r"(r[0]), "=r"(r[1]), "=r"(r[2]), "=r"(r[3]) : "r"(a));
}
__device__ __forceinline__ void mma16816(float* c, const uint32_t* a, const uint32_t* b) {
  asm volatile(
      "mma.sync.aligned.m16n8k16.row.col.f32.f16.f16.f32 "
      "{%0,%1,%2,%3}, {%4,%5,%6,%7}, {%8,%9}, {%0,%1,%2,%3};"
      : "+f"(c[0]), "+f"(c[1]), "+f"(c[2]), "+f"(c[3])
      : "r"(a[0]), "r"(a[1]), "r"(a[2]), "r"(a[3]), "r"(b[0]), "r"(b[1]));
}
__device__ __forceinline__ uint32_t pack2(float x, float y) {
  __half2 h = __floats2half2_rn(x, y);
  return *reinterpret_cast<uint32_t*>(&h);
}
__device__ __forceinline__ uint32_t ex2h2(uint32_t x) {
  uint32_t y;
  asm("ex2.approx.f16x2 %0, %1;" : "=r"(y) : "r"(x));
  return y;
}
__device__ __forceinline__ __half2 u2h2(uint32_t x) {
  return *reinterpret_cast<__half2*>(&x);
}
}  // namespace

// -------- prep: K,V fp32 -> fp16 ---------------------------------------------
__global__ void prep_kernel(const float* __restrict__ k, const float* __restrict__ v) {
  size_t i = (size_t)blockIdx.x * blockDim.x + threadIdx.x;
  const float4 fk = reinterpret_cast<const float4*>(k)[i];
  const float4 fv = reinterpret_cast<const float4*>(v)[i];
  reinterpret_cast<uint2*>(g_kh)[i] = make_uint2(pack2(fk.x, fk.y), pack2(fk.z, fk.w));
  reinterpret_cast<uint2*>(g_vh)[i] = make_uint2(pack2(fv.x, fv.y), pack2(fv.z, fv.w));
}

// -------- main attention kernel (one KV half per CTA) -------------------------
__global__ __launch_bounds__(NTH, 2)
void fa_hmma_kernel(const float* __restrict__ qg) {
  extern __shared__ __half sm[];
  __shared__ uint64_t barsto[2 * NBUF];
  __shared__ int srank;
  const uint32_t sb = s2u(sm);
  const uint32_t bfull = s2u(&barsto[0]);
  const uint32_t bempty = s2u(&barsto[NBUF]);

  const int tid = threadIdx.x;
  const int lane = tid & 31, warp = tid >> 5;
  const int mi = lane >> 3;
  const int li = lane & 7;
  const int bh = blockIdx.y, mblk = blockIdx.x, half = blockIdx.z;

  const float* qsrc = qg + ((size_t)bh * NSEQ + (size_t)mblk * BM) * DH;
  const __half* ksrc = g_kh + ((size_t)bh * NSEQ + (size_t)half * NKV_L * BN) * DH;
  const __half* vsrc = g_vh + ((size_t)bh * NSEQ + (size_t)half * NKV_L * BN) * DH;
  float* odst = (half ? g_oB : g_oA);
  float* ldst = (half ? g_lB : g_lA);

  if (tid == 0) {
#pragma unroll
    for (int i = 0; i < NBUF; i++) {
      mbar_init(bfull + 8 * i, NTH);
      mbar_init(bempty + 8 * i, NTH);
    }
    uint32_t smid;
    asm("mov.u32 %0, %%smid;" : "=r"(smid));
    srank = (int)(atomicAdd(&g_smctr[smid & 255], 1u) & 1u);
  }
  __syncthreads();

  // ---- prologue: start KV tile 0 into slot 0 (cp.async) ----
  {
#pragma unroll
    for (int i = 0; i < 8; i++) {
      int idx = i * NTH + tid;
      int r = idx >> 3, c = (idx & 7) << 3;
      cpa16(sb + (uint32_t)(r * LDS + c) * 2, ksrc + r * DH + c);
      cpa16(sb + (uint32_t)(BN * LDS + r * LDS + c) * 2, vsrc + r * DH + c);
    }
    cpa_arrive(bfull + 0);
  }
  // Q: fp32 LDG -> scale(log2 domain) -> fp16 STS into slot-2 staging area
#pragma unroll
  for (int i = 0; i < 16; i++) {
    int idx = i * NTH + tid;
    int r = idx >> 4, c = (idx & 15) << 2;
    float4 f = *reinterpret_cast<const float4*>(qsrc + r * DH + c);
    *reinterpret_cast<uint2*>(&sm[OQ + r * LDS + c]) =
        make_uint2(pack2(f.x * QS2, f.y * QS2), pack2(f.z * QS2, f.w * QS2));
  }
  __syncthreads();  // Q visible

  // ---- Q A-fragments (warp-M = 32) ----
  uint32_t qa[2][4][4];
#pragma unroll
  for (int s = 0; s < 2; s++)
#pragma unroll
    for (int kt = 0; kt < 4; kt++) {
      int row = warp * 32 + s * 16 + (mi & 1) * 8 + li;
      int col = kt * 16 + (mi >> 1) * 8;
      ldsm4(qa[s][kt], s2u(&sm[OQ + row * LDS + col]));
    }
  __syncthreads();  // slot 2 may now be overwritten

  // ---- cross-CTA phase stagger ----
  if (srank) {
    uint32_t t0 = (uint32_t)clock();
    while ((uint32_t)clock() - t0 < 1200u) {}
  }

  float oacc[2][8][4];
#pragma unroll
  for (int s = 0; s < 2; s++)
#pragma unroll
    for (int i = 0; i < 8; i++)
#pragma unroll
      for (int j = 0; j < 4; j++) oacc[s][i][j] = 0.f;
  float lsum[2][2] = {{0.f, 0.f}, {0.f, 0.f}};

#pragma unroll 1
  for (int t = 0; t < NKV_L; t++) {
    const int buf = t % 3;
    const int kb = buf * KVH;
    const int vb = kb + BN * LDS;

    // ---- prefetch tile t+1 (distance 1 at loop top) ----
    const int u = t + 1;
    if (u < NKV_L) {
      const int pb = u % 3;
      if (u >= 3) mbar_wait(bempty + 8 * pb, (uint32_t)(((u - 3) / 3) & 1));
      const __half* kn = ksrc + (size_t)u * BN * DH;
      const __half* vn = vsrc + (size_t)u * BN * DH;
      const int ob = pb * KVH;
#pragma unroll
      for (int i = 0; i < 8; i++) {
        int idx = i * NTH + tid;
        int r = idx >> 3, c = (idx & 7) << 3;
        cpa16(sb + (uint32_t)(ob + r * LDS + c) * 2, kn + r * DH + c);
        cpa16(sb + (uint32_t)(ob + BN * LDS + r * LDS + c) * 2, vn + r * DH + c);
      }
      cpa_arrive(bfull + 8 * pb);
    }

    mbar_wait(bfull + 8 * buf, (uint32_t)((t / 3) & 1));

    // ---- per-slice: S(s) -> exp -> PV(s) ----
#pragma unroll
    for (int s = 0; s < 2; s++) {
      float sacc[16][4];
#pragma unroll
      for (int i = 0; i < 16; i++)
#pragma unroll
        for (int j = 0; j < 4; j++) sacc[i][j] = 0.f;

#pragma unroll
      for (int kt = 0; kt < 4; kt++)
#pragma unroll
        for (int p = 0; p < 8; p++) {
          int row = p * 16 + (mi >> 1) * 8 + li;
          int col = kt * 16 + (mi & 1) * 8;
          uint32_t bf[4];
          ldsm4(bf, s2u(&sm[kb + row * LDS + col]));
          mma16816(sacc[2 * p], qa[s][kt], bf);
          mma16816(sacc[2 * p + 1], qa[s][kt], bf + 2);
        }

      __half2 a0 = __float2half2_rn(0.f), a1 = a0;
#pragma unroll
      for (int g = 0; g < 8; g++) {
        uint32_t pa[4];
        pa[0] = ex2h2(pack2(sacc[2 * g][0], sacc[2 * g][1]));
        pa[1] = ex2h2(pack2(sacc[2 * g][2], sacc[2 * g][3]));
        pa[2] = ex2h2(pack2(sacc[2 * g + 1][0], sacc[2 * g + 1][1]));
        pa[3] = ex2h2(pack2(sacc[2 * g + 1][2], sacc[2 * g + 1][3]));
        a0 = __hadd2(a0, __hadd2(u2h2(pa[0]), u2h2(pa[2])));
        a1 = __hadd2(a1, __hadd2(u2h2(pa[1]), u2h2(pa[3])));
#pragma unroll
        for (int d = 0; d < 4; d++) {
          int row = g * 16 + (mi & 1) * 8 + li;
          int col = (2 * d + (mi >> 1)) * 8;
          uint32_t bf[4];
          ldsm4t(bf, s2u(&sm[vb + row * LDS + col]));
          mma16816(oacc[s][2 * d], pa, bf);
          mma16816(oacc[s][2 * d + 1], pa, bf + 2);
        }
      }
      lsum[s][0] += __low2float(a0) + __high2float(a0);
      lsum[s][1] += __low2float(a1) + __high2float(a1);
    }

    mbar_arrive(bempty + 8 * buf);
  }

  // ---- epilogue: store additive partials (plain STG, own buffer) ----
#pragma unroll
  for (int s = 0; s < 2; s++)
#pragma unroll
    for (int h = 0; h < 2; h++) {
      float ls = lsum[s][h];
      ls += __shfl_xor_sync(0xffffffffu, ls, 1);
      ls += __shfl_xor_sync(0xffffffffu, ls, 2);
      int row = mblk * BM + warp * 32 + s * 16 + h * 8 + (lane >> 2);
      size_t grow = (size_t)bh * NSEQ + row;
      if ((lane & 3) == 0) ldst[grow] = ls;
      float* op = odst + grow * DH;
      int cb = (lane & 3) * 2;
#pragma unroll
      for (int nt = 0; nt < 8; nt++) {
        float2 f = make_float2(oacc[s][nt][2 * h], oacc[s][nt][2 * h + 1]);
        *reinterpret_cast<float2*>(op + nt * 8 + cb) = f;
      }
    }
}

// -------- combine: out = (A + B) / max(lA + lB, eps) --------------------------
__global__ void norm_kernel(float* __restrict__ out) {
  size_t i = (size_t)blockIdx.x * blockDim.x + threadIdx.x;  // float4 index
  float4 a = reinterpret_cast<const float4*>(g_oA)[i];
  float4 b = reinterpret_cast<const float4*>(g_oB)[i];
  size_t row = i >> 4;  // 16 float4 per 64-elem row
  float inv = 1.0f / fmaxf(g_lA[row] + g_lB[row], 1e-6f);
  float4 r;
  r.x = (a.x + b.x) * inv;
  r.y = (a.y + b.y) * inv;
  r.z = (a.z + b.z) * inv;
  r.w = (a.w + b.w) * inv;
  reinterpret_cast<float4*>(out)[i] = r;
}

extern "C" void kernel_launch(void* const* d_in, const int* in_sizes, int n_in,
                              void* d_out, int out_size) {
  const float* q = (const float*)d_in[0];
  const float* k = (const float*)d_in[1];
  const float* v = (const float*)d_in[2];
  float* out = (float*)d_out;

  prep_kernel<<<(int)(ELEMS / 4 / 256), 256>>>(k, v);

  cudaFuncSetAttribute(fa_hmma_kernel, cudaFuncAttributeMaxDynamicSharedMemorySize,
                       SMEM_BYTES);
  dim3 grid(NSEQ / BM, BHn, 2);  // 2048 units
  fa_hmma_kernel<<<grid, NTH, SMEM_BYTES>>>(q);

  norm_kernel<<<(int)(ELEMS / 4 / 256), 256>>>(out);
}

// round 17
// speedup vs baseline: 1.0812x; 1.0369x over previous
#include <cuda_runtime.h>
#include <cuda_fp16.h>
#include <cstdint>

// FlashAttention B=2,H=16,N=4096,D=64 fp32. logits=(q.k)/64.
// HMMA mma.sync fp16 path (plain-sm_103 toolchain; tcgen05/fp8 ruled out).
// R16 = R13 (best: BM=128/warp-M=32, BN=128, NBUF=3 ring, dist-1 prefetch,
// Q aliased in ring slot 2, per-SM stagger) + higher-MLP prep kernel.
// Structural note: per SM/tile the smem crossbar moves ~327KB (LDSM+STS) =
// ~93% of capacity while tensor sits at 74% -> kernel is crossbar+tensor
// co-bound; warp-M=64 (the fix) needs ~287 regs and spills. This is the
// mma.sync floor for this decomposition.

namespace {
constexpr int BHn = 32;
constexpr int NSEQ = 4096;
constexpr int DH = 64;
constexpr int BM = 128;
constexpr int BN = 128;
constexpr int NKV = NSEQ / BN;  // 32
constexpr int NTH = 128;        // 4 warps, warp-M = 32
constexpr int LDS = 72;         // smem row stride (halves)
constexpr int NBUF = 3;
constexpr float QS2 = 1.4426950408889634f / 64.0f;  // log2(e)/64
constexpr size_t ELEMS = (size_t)BHn * NSEQ * DH;

__device__ __half g_kh[ELEMS];
__device__ __half g_vh[ELEMS];
__device__ unsigned int g_smctr[256];  // per-SM arrival counters

// smem (halves): ring slot i at i*KVH (K then V). Q staging aliases slot 2.
constexpr int KVH = 2 * BN * LDS;  // 18432 halves per buffer
constexpr int OQ = 2 * KVH;        // Q staging = slot 2 (first written at t=2)
constexpr int SMEM_BYTES = NBUF * KVH * 2;  // 110592 B

__device__ __forceinline__ uint32_t s2u(const void* p) {
  return (uint32_t)__cvta_generic_to_shared(p);
}
__device__ __forceinline__ void cpa16(uint32_t dst, const void* src) {
  asm volatile("cp.async.cg.shared.global [%0], [%1], 16;" :: "r"(dst), "l"(src));
}
__device__ __forceinline__ void mbar_init(uint32_t a, uint32_t c) {
  asm volatile("mbarrier.init.shared.b64 [%0], %1;" :: "r"(a), "r"(c) : "memory");
}
__device__ __forceinline__ void mbar_arrive(uint32_t a) {
  asm volatile("mbarrier.arrive.shared.b64 _, [%0];" :: "r"(a) : "memory");
}
__device__ __forceinline__ void cpa_arrive(uint32_t a) {
  asm volatile("cp.async.mbarrier.arrive.noinc.shared.b64 [%0];" :: "r"(a) : "memory");
}
__device__ __forceinline__ void mbar_wait(uint32_t a, uint32_t ph) {
  asm volatile(
      "{\n\t.reg .pred P;\n"
      "W%=:\n\t"
      "mbarrier.try_wait.parity.acquire.cta.shared::cta.b64 P, [%0], %1, 0x989680;\n\t"
      "@P bra D%=;\n\t"
      "bra W%=;\n"
      "D%=:\n\t}"
      :: "r"(a), "r"(ph) : "memory");
}
__device__ __forceinline__ void ldsm4(uint32_t* r, uint32_t a) {
  asm volatile("ldmatrix.sync.aligned.m8n8.x4.shared.b16 {%0,%1,%2,%3}, [%4];"
               : "=r"(r[0]), "=r"(r[1]), "=r"(r[2]), "=r"(r[3]) : "r"(a));
}
__device__ __forceinline__ void ldsm4t(uint32_t* r, uint32_t a) {
  asm volatile("ldmatrix.sync.aligned.m8n8.x4.trans.shared.b16 {%0,%1,%2,%3}, [%4];"
               : "=r"(r[0]), "=r"(r[1]), "=r"(r[2]), "=r"(r[3]) : "r"(a));
}
__device__ __forceinline__ void mma16816(float* c, const uint32_t* a, const uint32_t* b) {
  asm volatile(
      "mma.sync.aligned.m16n8k16.row.col.f32.f16.f16.f32 "
      "{%0,%1,%2,%3}, {%4,%5,%6,%7}, {%8,%9}, {%0,%1,%2,%3};"
      : "+f"(c[0]), "+f"(c[1]), "+f"(c[2]), "+f"(c[3])
      : "r"(a[0]), "r"(a[1]), "r"(a[2]), "r"(a[3]), "r"(b[0]), "r"(b[1]));
}
__device__ __forceinline__ uint32_t pack2(float x, float y) {
  __half2 h = __floats2half2_rn(x, y);
  return *reinterpret_cast<uint32_t*>(&h);
}
__device__ __forceinline__ uint32_t ex2h2(uint32_t x) {
  uint32_t y;
  asm("ex2.approx.f16x2 %0, %1;" : "=r"(y) : "r"(x));
  return y;
}
__device__ __forceinline__ __half2 u2h2(uint32_t x) {
  return *reinterpret_cast<__half2*>(&x);
}
}  // namespace

// -------- prep: K,V fp32 -> fp16, 4 float4-pairs per thread (MLP=8) ----------
__global__ void prep_kernel(const float* __restrict__ k, const float* __restrict__ v) {
  size_t base = ((size_t)blockIdx.x * blockDim.x + threadIdx.x) * 4;
  float4 fk[4], fv[4];
#pragma unroll
  for (int j = 0; j < 4; j++) fk[j] = reinterpret_cast<const float4*>(k)[base + j];
#pragma unroll
  for (int j = 0; j < 4; j++) fv[j] = reinterpret_cast<const float4*>(v)[base + j];
#pragma unroll
  for (int j = 0; j < 4; j++) {
    reinterpret_cast<uint2*>(g_kh)[base + j] =
        make_uint2(pack2(fk[j].x, fk[j].y), pack2(fk[j].z, fk[j].w));
    reinterpret_cast<uint2*>(g_vh)[base + j] =
        make_uint2(pack2(fv[j].x, fv[j].y), pack2(fv[j].z, fv[j].w));
  }
}

// -------- main attention kernel ----------------------------------------------
__global__ __launch_bounds__(NTH, 2)
void fa_hmma_kernel(const float* __restrict__ qg, float* __restrict__ out) {
  extern __shared__ __half sm[];
  __shared__ uint64_t barsto[2 * NBUF];  // full[0..2], empty[0..2]
  __shared__ int srank;
  const uint32_t sb = s2u(sm);
  const uint32_t bfull = s2u(&barsto[0]);
  const uint32_t bempty = s2u(&barsto[NBUF]);

  const int tid = threadIdx.x;
  const int lane = tid & 31, warp = tid >> 5;
  const int mi = lane >> 3;
  const int li = lane & 7;
  const int bh = blockIdx.y, mblk = blockIdx.x;

  const float* qsrc = qg + ((size_t)bh * NSEQ + (size_t)mblk * BM) * DH;
  const __half* ksrc = g_kh + (size_t)bh * NSEQ * DH;
  const __half* vsrc = g_vh + (size_t)bh * NSEQ * DH;

  if (tid == 0) {
#pragma unroll
    for (int i = 0; i < NBUF; i++) {
      mbar_init(bfull + 8 * i, NTH);
      mbar_init(bempty + 8 * i, NTH);
    }
    uint32_t smid;
    asm("mov.u32 %0, %%smid;" : "=r"(smid));
    srank = (int)(atomicAdd(&g_smctr[smid & 255], 1u) & 1u);
  }
  __syncthreads();

  // ---- prologue: start KV tile 0 into slot 0 (cp.async) ----
  {
#pragma unroll
    for (int i = 0; i < 8; i++) {  // K: 128 rows x 8 chunks; V same
      int idx = i * NTH + tid;
      int r = idx >> 3, c = (idx & 7) << 3;
      cpa16(sb + (uint32_t)(r * LDS + c) * 2, ksrc + r * DH + c);
      cpa16(sb + (uint32_t)(BN * LDS + r * LDS + c) * 2, vsrc + r * DH + c);
    }
    cpa_arrive(bfull + 0);
  }
  // Q: fp32 LDG -> scale(log2 domain) -> fp16 STS into slot-2 staging area
#pragma unroll
  for (int i = 0; i < 16; i++) {
    int idx = i * NTH + tid;
    int r = idx >> 4, c = (idx & 15) << 2;
    float4 f = *reinterpret_cast<const float4*>(qsrc + r * DH + c);
    *reinterpret_cast<uint2*>(&sm[OQ + r * LDS + c]) =
        make_uint2(pack2(f.x * QS2, f.y * QS2), pack2(f.z * QS2, f.w * QS2));
  }
  __syncthreads();  // Q visible

  // ---- Q A-fragments (warp-M = 32) ----
  uint32_t qa[2][4][4];
#pragma unroll
  for (int s = 0; s < 2; s++)
#pragma unroll
    for (int kt = 0; kt < 4; kt++) {
      int row = warp * 32 + s * 16 + (mi & 1) * 8 + li;
      int col = kt * 16 + (mi >> 1) * 8;
      ldsm4(qa[s][kt], s2u(&sm[OQ + row * LDS + col]));
    }
  __syncthreads();  // all warps done reading Q: slot 2 may be overwritten

  // ---- cross-CTA phase stagger ----
  if (srank) {
    uint32_t t0 = (uint32_t)clock();
    while ((uint32_t)clock() - t0 < 1200u) {}
  }

  float oacc[2][8][4];
#pragma unroll
  for (int s = 0; s < 2; s++)
#pragma unroll
    for (int i = 0; i < 8; i++)
#pragma unroll
      for (int j = 0; j < 4; j++) oacc[s][i][j] = 0.f;
  float lsum[2][2] = {{0.f, 0.f}, {0.f, 0.f}};

#pragma unroll 1
  for (int t = 0; t < NKV; t++) {
    const int buf = t % 3;
    const int kb = buf * KVH;
    const int vb = kb + BN * LDS;

    // ---- prefetch tile t+1 (distance 1 at loop top: slack = 1 full tile) ----
    const int u = t + 1;
    if (u < NKV) {
      const int pb = u % 3;
      if (u >= 3) mbar_wait(bempty + 8 * pb, (uint32_t)(((u - 3) / 3) & 1));
      const __half* kn = ksrc + (size_t)u * BN * DH;
      const __half* vn = vsrc + (size_t)u * BN * DH;
      const int ob = pb * KVH;
#pragma unroll
      for (int i = 0; i < 8; i++) {
        int idx = i * NTH + tid;
        int r = idx >> 3, c = (idx & 7) << 3;
        cpa16(sb + (uint32_t)(ob + r * LDS + c) * 2, kn + r * DH + c);
        cpa16(sb + (uint32_t)(ob + BN * LDS + r * LDS + c) * 2, vn + r * DH + c);
      }
      cpa_arrive(bfull + 8 * pb);
    }

    mbar_wait(bfull + 8 * buf, (uint32_t)((t / 3) & 1));

    // ---- per-slice: S(s) -> exp -> PV(s); one slice's sacc live at a time ----
#pragma unroll
    for (int s = 0; s < 2; s++) {
      float sacc[16][4];
#pragma unroll
      for (int i = 0; i < 16; i++)
#pragma unroll
        for (int j = 0; j < 4; j++) sacc[i][j] = 0.f;

#pragma unroll
      for (int kt = 0; kt < 4; kt++)
#pragma unroll
        for (int p = 0; p < 8; p++) {
          int row = p * 16 + (mi >> 1) * 8 + li;
          int col = kt * 16 + (mi & 1) * 8;
          uint32_t bf[4];
          ldsm4(bf, s2u(&sm[kb + row * LDS + col]));
          mma16816(sacc[2 * p], qa[s][kt], bf);
          mma16816(sacc[2 * p + 1], qa[s][kt], bf + 2);
        }

      __half2 a0 = __float2half2_rn(0.f), a1 = a0;
#pragma unroll
      for (int g = 0; g < 8; g++) {
        uint32_t pa[4];
        pa[0] = ex2h2(pack2(sacc[2 * g][0], sacc[2 * g][1]));
        pa[1] = ex2h2(pack2(sacc[2 * g][2], sacc[2 * g][3]));
        pa[2] = ex2h2(pack2(sacc[2 * g + 1][0], sacc[2 * g + 1][1]));
        pa[3] = ex2h2(pack2(sacc[2 * g + 1][2], sacc[2 * g + 1][3]));
        a0 = __hadd2(a0, __hadd2(u2h2(pa[0]), u2h2(pa[2])));
        a1 = __hadd2(a1, __hadd2(u2h2(pa[1]), u2h2(pa[3])));
#pragma unroll
        for (int d = 0; d < 4; d++) {
          int row = g * 16 + (mi & 1) * 8 + li;
          int col = (2 * d + (mi >> 1)) * 8;
          uint32_t bf[4];
          ldsm4t(bf, s2u(&sm[vb + row * LDS + col]));
          mma16816(oacc[s][2 * d], pa, bf);
          mma16816(oacc[s][2 * d + 1], pa, bf + 2);
        }
      }
      lsum[s][0] += __low2float(a0) + __high2float(a0);
      lsum[s][1] += __low2float(a1) + __high2float(a1);
    }

    mbar_arrive(bempty + 8 * buf);  // done reading buf
  }

  // ---- epilogue: O / max(l, eps) ----
#pragma unroll
  for (int s = 0; s < 2; s++)
#pragma unroll
    for (int h = 0; h < 2; h++) {
      float ls = lsum[s][h];
      ls += __shfl_xor_sync(0xffffffffu, ls, 1);
      ls += __shfl_xor_sync(0xffffffffu, ls, 2);
      float inv = 1.0f / fmaxf(ls, 1e-6f);
      int row = mblk * BM + warp * 32 + s * 16 + h * 8 + (lane >> 2);
      float* op = out + ((size_t)bh * NSEQ + row) * DH;
      int cb = (lane & 3) * 2;
#pragma unroll
      for (int nt = 0; nt < 8; nt++) {
        float2 f = make_float2(oacc[s][nt][2 * h] * inv, oacc[s][nt][2 * h + 1] * inv);
        *reinterpret_cast<float2*>(op + nt * 8 + cb) = f;
      }
    }
}

extern "C" void kernel_launch(void* const* d_in, const int* in_sizes, int n_in,
                              void* d_out, int out_size) {
  const float* q = (const float*)d_in[0];
  const float* k = (const float*)d_in[1];
  const float* v = (const float*)d_in[2];
  float* out = (float*)d_out;

  prep_kernel<<<(int)(ELEMS / 16 / 256), 256>>>(k, v);

  cudaFuncSetAttribute(fa_hmma_kernel, cudaFuncAttributeMaxDynamicSharedMemorySize,
                       SMEM_BYTES);
  dim3 grid(NSEQ / BM, BHn);  // (32, 32)
  fa_hmma_kernel<<<grid, NTH, SMEM_BYTES>>>(q, out);
}